// round 1
// baseline (speedup 1.0000x reference)
#include <cuda_runtime.h>

#define BB   8
#define NN   128
#define COOR 3
#define FF   128
#define FILT 128

// Scratch: A' = x @ w1 + bv  and  C = x @ w2, each [B, N, COOR, FILT]
__device__ float g_A[BB * NN * COOR * FILT];
__device__ float g_C[BB * NN * COOR * FILT];

// ---------------------------------------------------------------------------
// Phase 1: tiny GEMM [3072, 128] @ [128, 256]  ->  g_A (with +bv), g_C
// 8 GEMM rows per block share the w-column loads. 128 threads = one k each.
// ---------------------------------------------------------------------------
__global__ __launch_bounds__(128) void phase1_kernel(
    const float* __restrict__ x,   // [B*N*COOR, F] flattened
    const float* __restrict__ w,   // [2F, FILT]
    const float* __restrict__ bv)  // [FILT]
{
    constexpr int ROWS = 8;
    const int r0 = blockIdx.x * ROWS;   // 0..3064
    const int k  = threadIdx.x;         // 0..127

    __shared__ float xs[ROWS][FF];

    // Load 8 contiguous x rows (8*128 floats) coalesced as float4.
    const float4* xin = reinterpret_cast<const float4*>(x + (size_t)r0 * FF);
    float4* xs4 = reinterpret_cast<float4*>(&xs[0][0]);
    #pragma unroll
    for (int t = threadIdx.x; t < ROWS * FF / 4; t += 128) xs4[t] = xin[t];
    __syncthreads();

    float accA[ROWS], accC[ROWS];
    const float bvk = bv[k];
    #pragma unroll
    for (int r = 0; r < ROWS; r++) { accA[r] = bvk; accC[r] = 0.0f; }

    #pragma unroll 4
    for (int f = 0; f < FF; f++) {
        const float w1 = w[f * FILT + k];          // coalesced over threads
        const float w2 = w[(FF + f) * FILT + k];
        #pragma unroll
        for (int r = 0; r < ROWS; r++) {
            const float xv = xs[r][f];             // smem broadcast
            accA[r] = fmaf(xv, w1, accA[r]);
            accC[r] = fmaf(xv, w2, accC[r]);
        }
    }

    #pragma unroll
    for (int r = 0; r < ROWS; r++) {
        g_A[(size_t)(r0 + r) * FILT + k] = accA[r];
        g_C[(size_t)(r0 + r) * FILT + k] = accC[r];
    }
}

// ---------------------------------------------------------------------------
// Phase 2: out[b,i,j,k] = sum_c (A'[b,i,c,k] + C[b,j,c,k]) * d[b,i,j,c]
// Block = (32,8): tx indexes k as float4 (32*4 = 128 k), ty strides over j.
// Each block owns TI=4 consecutive i rows; A' tile lives in registers,
// the distances slice [TI,128,3] lives in smem (warp-broadcast reads).
// ---------------------------------------------------------------------------
__global__ __launch_bounds__(256) void phase2_kernel(
    const float* __restrict__ dist,  // [B, N, N, COOR]
    float* __restrict__ out)         // [B, N, N, FILT]
{
    constexpr int TI = 4;
    const int b  = blockIdx.y;
    const int i0 = blockIdx.x * TI;
    const int tx = threadIdx.x;   // 0..31
    const int ty = threadIdx.y;   // 0..7
    const int tid = ty * 32 + tx;

    __shared__ float sd[TI * NN * COOR];   // 1536 floats = 6 KB

    // Load distances slice d[b, i0:i0+4, :, :] (contiguous 1536 floats).
    {
        const float4* din =
            reinterpret_cast<const float4*>(dist + (size_t)(b * NN + i0) * NN * COOR);
        float4* sd4 = reinterpret_cast<float4*>(sd);
        #pragma unroll
        for (int t = tid; t < TI * NN * COOR / 4; t += 256) sd4[t] = din[t];
    }

    // A' tile into registers: 4 i x 3 c x float4 = 48 floats.
    float4 Ar[TI][COOR];
    {
        const float4* A4 = reinterpret_cast<const float4*>(g_A);
        #pragma unroll
        for (int i = 0; i < TI; i++)
            #pragma unroll
            for (int c = 0; c < COOR; c++)
                Ar[i][c] = A4[((size_t)(b * NN + i0 + i) * COOR + c) * (FILT / 4) + tx];
    }
    __syncthreads();

    const float4* C4 = reinterpret_cast<const float4*>(g_C);
    float4* out4 = reinterpret_cast<float4*>(out);

    for (int j = ty; j < NN; j += 8) {
        const size_t cb = (size_t)(b * NN + j) * COOR * (FILT / 4);
        const float4 c0 = C4[cb + 0 * (FILT / 4) + tx];
        const float4 c1 = C4[cb + 1 * (FILT / 4) + tx];
        const float4 c2 = C4[cb + 2 * (FILT / 4) + tx];

        #pragma unroll
        for (int i = 0; i < TI; i++) {
            const float d0 = sd[(i * NN + j) * COOR + 0];  // warp broadcast
            const float d1 = sd[(i * NN + j) * COOR + 1];
            const float d2 = sd[(i * NN + j) * COOR + 2];

            float4 o;
            o.x = fmaf(Ar[i][0].x + c0.x, d0,
                  fmaf(Ar[i][1].x + c1.x, d1, (Ar[i][2].x + c2.x) * d2));
            o.y = fmaf(Ar[i][0].y + c0.y, d0,
                  fmaf(Ar[i][1].y + c1.y, d1, (Ar[i][2].y + c2.y) * d2));
            o.z = fmaf(Ar[i][0].z + c0.z, d0,
                  fmaf(Ar[i][1].z + c1.z, d1, (Ar[i][2].z + c2.z) * d2));
            o.w = fmaf(Ar[i][0].w + c0.w, d0,
                  fmaf(Ar[i][1].w + c1.w, d1, (Ar[i][2].w + c2.w) * d2));

            out4[((size_t)(b * NN + i0 + i) * NN + j) * (FILT / 4) + tx] = o;
        }
    }
}

extern "C" void kernel_launch(void* const* d_in, const int* in_sizes, int n_in,
                              void* d_out, int out_size)
{
    const float* x    = (const float*)d_in[0];  // vector_features [8,128,3,128]
    const float* dist = (const float*)d_in[1];  // distances       [8,128,128,3]
    const float* w    = (const float*)d_in[2];  // w_vs            [256,128]
    const float* bv   = (const float*)d_in[3];  // b_vs            [128]
    float* out = (float*)d_out;                 // [8,128,128,128]

    (void)in_sizes; (void)n_in; (void)out_size;

    phase1_kernel<<<(BB * NN * COOR) / 8, 128>>>(x, w, bv);
    phase2_kernel<<<dim3(NN / 4, BB), dim3(32, 8)>>>(dist, out);
}